// round 2
// baseline (speedup 1.0000x reference)
#include <cuda_runtime.h>
#include <cstdint>
#include <float.h>

#define NROWS 2048
#define VV    50257
#define VPAD  50260          // padded to multiple of 4
#define NV4   12565          // VPAD / 4
#define EE    64
#define KSEL  250
#define NT    512
#define BUFCAP 1024

struct __align__(16) Smem {
    float srow[VPAD];                 // 201,040 B
    unsigned long long buf[BUFCAP];   //   8,192 B
    float su[EE];                     //     256 B
    float red[32];
    int   icnt[8];    // [0..3] threshold counts, [4] collect counter
    float fctl[8];    // [0]=lo [1]=hi [2]=Tsel [3]=c0
    int   ictl[4];    // [0]=done [1]=n_lo
};

__global__ void __launch_bounds__(NT, 1) lang_topk_kernel(
    const float* __restrict__ gx, const float* __restrict__ cb,
    const float* __restrict__ W,  const float* __restrict__ logits,
    float* __restrict__ out)
{
    extern __shared__ char smraw[];
    Smem& sm = *reinterpret_cast<Smem*>(smraw);
    const int tid = threadIdx.x;
    const int row = blockIdx.x;
    const float* lrow = logits + (size_t)row * VV;

    // ---------------- stage row into smem, fused min/max ----------------
    float mx = -FLT_MAX, mn = FLT_MAX;
    {
        uintptr_t a = (uintptr_t)lrow;
        int lead = (int)(((16u - (unsigned)(a & 15u)) & 15u) >> 2);  // 0..3
        for (int i = tid; i < lead; i += NT) {
            float x = lrow[i]; sm.srow[i] = x;
            mx = fmaxf(mx, x); mn = fminf(mn, x);
        }
        int nv4 = (VV - lead) >> 2;
        const float4* l4 = reinterpret_cast<const float4*>(lrow + lead);
        for (int i = tid; i < nv4; i += NT) {
            float4 x = l4[i];
            int b = lead + i * 4;
            sm.srow[b+0] = x.x; sm.srow[b+1] = x.y;
            sm.srow[b+2] = x.z; sm.srow[b+3] = x.w;
            mx = fmaxf(mx, fmaxf(fmaxf(x.x, x.y), fmaxf(x.z, x.w)));
            mn = fminf(mn, fminf(fminf(x.x, x.y), fminf(x.z, x.w)));
        }
        for (int i = lead + nv4 * 4 + tid; i < VV; i += NT) {
            float x = lrow[i]; sm.srow[i] = x;
            mx = fmaxf(mx, x); mn = fminf(mn, x);
        }
        for (int i = VV + tid; i < VPAD; i += NT) sm.srow[i] = -FLT_MAX;
    }
    // block reduce min/max
    #pragma unroll
    for (int o = 16; o; o >>= 1) {
        mx = fmaxf(mx, __shfl_xor_sync(0xffffffffu, mx, o));
        mn = fminf(mn, __shfl_xor_sync(0xffffffffu, mn, o));
    }
    if ((tid & 31) == 0) { sm.red[tid >> 5] = mx; sm.red[16 + (tid >> 5)] = mn; }
    __syncthreads();
    if (tid == 0) {
        float M = -FLT_MAX, m = FLT_MAX;
        for (int w = 0; w < 16; ++w) {
            M = fmaxf(M, sm.red[w]); m = fminf(m, sm.red[16 + w]);
        }
        sm.fctl[0] = m; sm.fctl[1] = M;
        sm.ictl[0] = 0; sm.ictl[1] = VV;
        sm.icnt[0] = sm.icnt[1] = sm.icnt[2] = sm.icnt[3] = 0;
        sm.icnt[4] = 0;
    }
    __syncthreads();

    // ---------------- threshold bracketing: 4-point count scans ----------------
    const float4* s4 = reinterpret_cast<const float4*>(sm.srow);
    for (int it = 0; it < 14; ++it) {
        if (sm.ictl[0]) break;                 // uniform (post-barrier)
        float lo = sm.fctl[0], hi = sm.fctl[1];
        float step = (hi - lo) * 0.2f;
        float t0 = lo + step, t1 = lo + 2.f*step, t2 = lo + 3.f*step, t3 = lo + 4.f*step;
        int c0 = 0, c1 = 0, c2 = 0, c3 = 0;
        for (int i = tid; i < NV4; i += NT) {
            float4 x = s4[i];
            c0 += (x.x>=t0)+(x.y>=t0)+(x.z>=t0)+(x.w>=t0);
            c1 += (x.x>=t1)+(x.y>=t1)+(x.z>=t1)+(x.w>=t1);
            c2 += (x.x>=t2)+(x.y>=t2)+(x.z>=t2)+(x.w>=t2);
            c3 += (x.x>=t3)+(x.y>=t3)+(x.z>=t3)+(x.w>=t3);
        }
        #pragma unroll
        for (int o = 16; o; o >>= 1) {
            c0 += __shfl_xor_sync(0xffffffffu, c0, o);
            c1 += __shfl_xor_sync(0xffffffffu, c1, o);
            c2 += __shfl_xor_sync(0xffffffffu, c2, o);
            c3 += __shfl_xor_sync(0xffffffffu, c3, o);
        }
        if ((tid & 31) == 0) {
            atomicAdd(&sm.icnt[0], c0); atomicAdd(&sm.icnt[1], c1);
            atomicAdd(&sm.icnt[2], c2); atomicAdd(&sm.icnt[3], c3);
        }
        __syncthreads();
        if (tid == 0) {
            int   n[5]  = { sm.ictl[1], sm.icnt[0], sm.icnt[1], sm.icnt[2], sm.icnt[3] };
            float tt[5] = { lo, t0, t1, t2, t3 };
            int j = 0;
            for (int q = 1; q < 5; ++q) if (n[q] >= KSEL) j = q;
            bool degen = !(t0 > lo && t3 < hi);
            if (n[j] <= BUFCAP || degen || it == 13) {
                sm.fctl[2] = tt[j]; sm.ictl[0] = 1;
            } else {
                sm.fctl[0] = tt[j]; sm.ictl[1] = n[j];
                sm.fctl[1] = (j < 4) ? tt[j + 1] : hi;
            }
            sm.icnt[0] = sm.icnt[1] = sm.icnt[2] = sm.icnt[3] = 0;
        }
        __syncthreads();
    }

    // ---------------- collect candidates (x >= T) as 64-bit composites ----------------
    {
        const float T = sm.fctl[2];
        #pragma unroll 1
        for (int it = 0; it < (NV4 + NT - 1) / NT; ++it) {
            int i = tid + it * NT;
            unsigned pr = 0;
            float4 x = make_float4(0.f, 0.f, 0.f, 0.f);
            if (i < NV4) {
                x = s4[i];
                pr = (x.x >= T ? 1u : 0u) | (x.y >= T ? 2u : 0u)
                   | (x.z >= T ? 4u : 0u) | (x.w >= T ? 8u : 0u);
            }
            if (__ballot_sync(0xffffffffu, pr != 0u)) {
                if (pr) {
                    int base = atomicAdd(&sm.icnt[4], __popc(pr));
                    float vals[4] = { x.x, x.y, x.z, x.w };
                    unsigned idx0 = (unsigned)i * 4u;
                    #pragma unroll
                    for (int c = 0; c < 4; ++c) {
                        if (pr & (1u << c)) {
                            unsigned ub  = __float_as_uint(vals[c]);
                            unsigned key = (ub & 0x80000000u) ? ~ub : (ub | 0x80000000u);
                            if (base < BUFCAP)
                                sm.buf[base] =
                                    ((unsigned long long)key << 32) | (unsigned)(~(idx0 + c));
                            ++base;
                        }
                    }
                }
            }
        }
    }
    __syncthreads();
    const int C = min(sm.icnt[4], BUFCAP);

    // pad buffer
    for (int i = C + tid; i < BUFCAP; i += NT) sm.buf[i] = 0ull;

    // ---------------- u vector and c0 scalar for this row ----------------
    if (tid < EE) {
        float g = gx[row * EE + tid], c = cb[row * EE + tid];
        sm.su[tid] = -0.5f * g + 20.0f * c;
        float p = 0.5f * g * c - 10.0f * c * c;
        #pragma unroll
        for (int o = 16; o; o >>= 1) p += __shfl_xor_sync(0xffffffffu, p, o);
        if ((tid & 31) == 0) sm.red[tid >> 5] = p;
    }
    __syncthreads();
    if (tid == 0) sm.fctl[3] = sm.red[0] + sm.red[1];

    // ---------------- bitonic sort 1024 composites, descending ----------------
    for (unsigned k = 2; k <= BUFCAP; k <<= 1) {
        for (unsigned j = k >> 1; j > 0; j >>= 1) {
            __syncthreads();
            unsigned i = ((unsigned)tid << 1) - ((unsigned)tid & (j - 1));
            unsigned p = i | j;
            unsigned long long a = sm.buf[i], b = sm.buf[p];
            bool desc = ((i & k) == 0);
            if (desc ? (a < b) : (a > b)) { sm.buf[i] = b; sm.buf[p] = a; }
        }
    }
    __syncthreads();

    // ---------------- gather: filtered value + id for top-250 ----------------
    if (tid < KSEL) {
        unsigned long long comp = sm.buf[tid];
        unsigned idx = ~((unsigned)(comp & 0xffffffffull));
        const float4* wr = reinterpret_cast<const float4*>(W + (size_t)idx * EE);
        const float4* u4 = reinterpret_cast<const float4*>(sm.su);
        float acc = 0.f, wsq = 0.f;
        #pragma unroll
        for (int q = 0; q < EE / 4; ++q) {
            float4 w = wr[q], u = u4[q];
            acc += w.x * u.x + w.y * u.y + w.z * u.z + w.w * u.w;
            wsq += w.x * w.x + w.y * w.y + w.z * w.z + w.w * w.w;
        }
        float val = acc - 10.0f * wsq + sm.fctl[3];
        size_t o = (size_t)row * KSEL + (size_t)tid;
        out[o] = val;
        out[(size_t)NROWS * KSEL + o] = (float)idx;
    }
}

extern "C" void kernel_launch(void* const* d_in, const int* in_sizes, int n_in,
                              void* d_out, int out_size)
{
    (void)in_sizes; (void)n_in; (void)out_size;
    const float* gx = (const float*)d_in[0];
    const float* cb = (const float*)d_in[1];
    const float* W  = (const float*)d_in[2];
    const float* lg = (const float*)d_in[3];
    size_t smem = sizeof(Smem);
    cudaFuncSetAttribute(lang_topk_kernel,
                         cudaFuncAttributeMaxDynamicSharedMemorySize, (int)smem);
    lang_topk_kernel<<<NROWS, NT, smem>>>(gx, cb, W, lg, (float*)d_out);
}

// round 3
// speedup vs baseline: 2.2495x; 2.2495x over previous
#include <cuda_runtime.h>
#include <cstdint>
#include <float.h>

#define NROWS  2048
#define VV     50257
#define EE     64
#define KSEL   250
#define NT     512
#define BUFCAP 1024
#define T0     2.2f

__device__ __forceinline__ unsigned long long make_comp(float x, unsigned gidx) {
    unsigned ub  = __float_as_uint(x);
    unsigned key = (ub & 0x80000000u) ? ~ub : (ub | 0x80000000u);
    return ((unsigned long long)key << 32) | (unsigned)(~gidx);
}

__global__ void __launch_bounds__(NT, 3) lang_topk_kernel(
    const float* __restrict__ gx, const float* __restrict__ cb,
    const float* __restrict__ W,  const float* __restrict__ logits,
    float* __restrict__ out)
{
    __shared__ unsigned long long buf[BUFCAP];
    __shared__ float su[EE];
    __shared__ float red[32];
    __shared__ int   scnt;
    __shared__ int   icnt[4];
    __shared__ float fctl[4];   // [0]=lo [1]=hi [2]=Tsel [3]=c0
    __shared__ int   ictl[2];   // [0]=done [1]=n_lo

    const int tid = threadIdx.x;
    const int row = blockIdx.x;
    const float* __restrict__ lrow = logits + (size_t)row * VV;

    if (tid == 0) scnt = 0;
    // u vector + c0 partial sums (warps 0-1), concurrent with init
    if (tid < EE) {
        float g = gx[row * EE + tid], c = cb[row * EE + tid];
        su[tid] = -0.5f * g + 20.0f * c;
        float p = 0.5f * g * c - 10.0f * c * c;
        #pragma unroll
        for (int o = 16; o; o >>= 1) p += __shfl_xor_sync(0xffffffffu, p, o);
        if ((tid & 31) == 0) red[tid >> 5] = p;
    }
    __syncthreads();

    // alignment split
    uintptr_t a = (uintptr_t)lrow;
    const int lead = (int)(((16u - (unsigned)(a & 15u)) & 15u) >> 2);   // 0..3
    const int nv4  = (VV - lead) >> 2;
    const int tail0 = lead + nv4 * 4;
    const float4* __restrict__ l4 = reinterpret_cast<const float4*>(lrow + lead);

    // ------------- single-pass collect @ static threshold -------------
    float T = T0;
    for (int i = tid; i < lead; i += NT) {
        float x = lrow[i];
        if (x >= T) {
            int p = atomicAdd(&scnt, 1);
            if (p < BUFCAP) buf[p] = make_comp(x, (unsigned)i);
        }
    }
    #pragma unroll 4
    for (int i = tid; i < nv4; i += NT) {
        float4 x = l4[i];
        unsigned pr = (x.x >= T ? 1u : 0u) | (x.y >= T ? 2u : 0u)
                    | (x.z >= T ? 4u : 0u) | (x.w >= T ? 8u : 0u);
        if (pr) {
            int base = atomicAdd(&scnt, __popc(pr));
            float vals[4] = { x.x, x.y, x.z, x.w };
            unsigned g0 = (unsigned)(lead + 4 * i);
            #pragma unroll
            for (int c = 0; c < 4; ++c) {
                if (pr & (1u << c)) {
                    if (base < BUFCAP) buf[base] = make_comp(vals[c], g0 + c);
                    ++base;
                }
            }
        }
    }
    for (int i = tail0 + tid; i < VV; i += NT) {
        float x = lrow[i];
        if (x >= T) {
            int p = atomicAdd(&scnt, 1);
            if (p < BUFCAP) buf[p] = make_comp(x, (unsigned)i);
        }
    }
    __syncthreads();
    if (tid == 0) fctl[3] = red[0] + red[1];   // c0
    int C = scnt;

    // ------------- rare fallback: adaptive threshold from gmem (L2) -------------
    if (C < KSEL || C > BUFCAP) {
        __syncthreads();
        float mx = -FLT_MAX, mn = FLT_MAX;
        for (int i = tid; i < VV; i += NT) {
            float x = lrow[i];
            mx = fmaxf(mx, x); mn = fminf(mn, x);
        }
        #pragma unroll
        for (int o = 16; o; o >>= 1) {
            mx = fmaxf(mx, __shfl_xor_sync(0xffffffffu, mx, o));
            mn = fminf(mn, __shfl_xor_sync(0xffffffffu, mn, o));
        }
        if ((tid & 31) == 0) { red[tid >> 5] = mx; red[16 + (tid >> 5)] = mn; }
        __syncthreads();
        if (tid == 0) {
            float M = -FLT_MAX, m = FLT_MAX;
            for (int w = 0; w < 16; ++w) {
                M = fmaxf(M, red[w]); m = fminf(m, red[16 + w]);
            }
            if (C > BUFCAP) { fctl[0] = T0; fctl[1] = M; ictl[1] = C;  }
            else            { fctl[0] = m;  fctl[1] = T0; ictl[1] = VV; }
            ictl[0] = 0;
            icnt[0] = icnt[1] = icnt[2] = icnt[3] = 0;
        }
        __syncthreads();
        for (int it = 0; it < 30; ++it) {
            if (ictl[0]) break;
            float lo = fctl[0], hi = fctl[1];
            float step = (hi - lo) * 0.2f;
            float t0 = lo + step, t1 = lo + 2.f*step, t2 = lo + 3.f*step, t3 = lo + 4.f*step;
            int c0 = 0, c1 = 0, c2 = 0, c3 = 0;
            for (int i = tid; i < VV; i += NT) {
                float x = lrow[i];
                c0 += (x >= t0); c1 += (x >= t1); c2 += (x >= t2); c3 += (x >= t3);
            }
            #pragma unroll
            for (int o = 16; o; o >>= 1) {
                c0 += __shfl_xor_sync(0xffffffffu, c0, o);
                c1 += __shfl_xor_sync(0xffffffffu, c1, o);
                c2 += __shfl_xor_sync(0xffffffffu, c2, o);
                c3 += __shfl_xor_sync(0xffffffffu, c3, o);
            }
            if ((tid & 31) == 0) {
                atomicAdd(&icnt[0], c0); atomicAdd(&icnt[1], c1);
                atomicAdd(&icnt[2], c2); atomicAdd(&icnt[3], c3);
            }
            __syncthreads();
            if (tid == 0) {
                int   n[5]  = { ictl[1], icnt[0], icnt[1], icnt[2], icnt[3] };
                float tt[5] = { lo, t0, t1, t2, t3 };
                int j = 0;
                for (int q = 1; q < 5; ++q) if (n[q] >= KSEL) j = q;
                bool degen = !(t0 > lo && t3 < hi);
                if (n[j] <= BUFCAP || degen || it == 29) {
                    fctl[2] = tt[j]; ictl[0] = 1;
                } else {
                    fctl[0] = tt[j]; ictl[1] = n[j];
                    fctl[1] = (j < 4) ? tt[j + 1] : hi;
                }
                icnt[0] = icnt[1] = icnt[2] = icnt[3] = 0;
            }
            __syncthreads();
        }
        T = fctl[2];
        if (tid == 0) scnt = 0;
        __syncthreads();
        // recollect at final T
        for (int i = tid; i < lead; i += NT) {
            float x = lrow[i];
            if (x >= T) {
                int p = atomicAdd(&scnt, 1);
                if (p < BUFCAP) buf[p] = make_comp(x, (unsigned)i);
            }
        }
        for (int i = tid; i < nv4; i += NT) {
            float4 x = l4[i];
            unsigned pr = (x.x >= T ? 1u : 0u) | (x.y >= T ? 2u : 0u)
                        | (x.z >= T ? 4u : 0u) | (x.w >= T ? 8u : 0u);
            if (pr) {
                int base = atomicAdd(&scnt, __popc(pr));
                float vals[4] = { x.x, x.y, x.z, x.w };
                unsigned g0 = (unsigned)(lead + 4 * i);
                #pragma unroll
                for (int c = 0; c < 4; ++c) {
                    if (pr & (1u << c)) {
                        if (base < BUFCAP) buf[base] = make_comp(vals[c], g0 + c);
                        ++base;
                    }
                }
            }
        }
        for (int i = tail0 + tid; i < VV; i += NT) {
            float x = lrow[i];
            if (x >= T) {
                int p = atomicAdd(&scnt, 1);
                if (p < BUFCAP) buf[p] = make_comp(x, (unsigned)i);
            }
        }
        __syncthreads();
        C = scnt;
    }

    const int n = min(C, BUFCAP);
    for (int i = n + tid; i < BUFCAP; i += NT) buf[i] = 0ull;

    // ------------- bitonic sort 1024 composites, descending -------------
    for (unsigned k = 2; k <= BUFCAP; k <<= 1) {
        for (unsigned j = k >> 1; j > 0; j >>= 1) {
            __syncthreads();
            unsigned i = ((unsigned)tid << 1) - ((unsigned)tid & (j - 1));
            unsigned p = i | j;
            unsigned long long x = buf[i], y = buf[p];
            bool desc = ((i & k) == 0);
            if (desc ? (x < y) : (x > y)) { buf[i] = y; buf[p] = x; }
        }
    }
    __syncthreads();

    // ------------- gather: 250 dots against W -------------
    if (tid < KSEL) {
        unsigned idx = ~((unsigned)(buf[tid] & 0xffffffffull));
        const float4* wr = reinterpret_cast<const float4*>(W + (size_t)idx * EE);
        const float4* u4 = reinterpret_cast<const float4*>(su);
        float acc = 0.f, wsq = 0.f;
        #pragma unroll
        for (int q = 0; q < EE / 4; ++q) {
            float4 w = wr[q], u = u4[q];
            acc += w.x * u.x + w.y * u.y + w.z * u.z + w.w * u.w;
            wsq += w.x * w.x + w.y * w.y + w.z * w.z + w.w * w.w;
        }
        size_t o = (size_t)row * KSEL + (size_t)tid;
        out[o] = acc - 10.0f * wsq + fctl[3];
        out[(size_t)NROWS * KSEL + o] = (float)idx;
    }
}

extern "C" void kernel_launch(void* const* d_in, const int* in_sizes, int n_in,
                              void* d_out, int out_size)
{
    (void)in_sizes; (void)n_in; (void)out_size;
    lang_topk_kernel<<<NROWS, NT>>>(
        (const float*)d_in[0], (const float*)d_in[1],
        (const float*)d_in[2], (const float*)d_in[3], (float*)d_out);
}

// round 4
// speedup vs baseline: 2.5815x; 1.1476x over previous
#include <cuda_runtime.h>
#include <cstdint>
#include <float.h>

#define NROWS  2048
#define VV     50257
#define EE     64
#define KSEL   250
#define NT     256
#define BUFCAP 512
#define T0     2.45f

__device__ __forceinline__ unsigned long long make_comp(float x, unsigned gidx) {
    unsigned ub  = __float_as_uint(x);
    unsigned key = (ub & 0x80000000u) ? ~ub : (ub | 0x80000000u);
    return ((unsigned long long)key << 32) | (unsigned)(~gidx);
}

__global__ void __launch_bounds__(NT, 6) lang_topk_kernel(
    const float* __restrict__ gx, const float* __restrict__ cb,
    const float* __restrict__ W,  const float* __restrict__ logits,
    float* __restrict__ out)
{
    __shared__ unsigned long long buf[BUFCAP];
    __shared__ float su[EE];
    __shared__ float red[16];
    __shared__ int   scnt;
    __shared__ int   icnt[4];
    __shared__ float fctl[4];   // [0]=lo [1]=hi [2]=Tsel [3]=c0
    __shared__ int   ictl[2];   // [0]=done [1]=n_lo

    const int tid = threadIdx.x;
    const int row = blockIdx.x;
    const float* __restrict__ lrow = logits + (size_t)row * VV;

    if (tid == 0) scnt = 0;
    // u vector + c0 partial sums (warps 0-1)
    if (tid < EE) {
        float g = gx[row * EE + tid], c = cb[row * EE + tid];
        su[tid] = -0.5f * g + 20.0f * c;
        float p = 0.5f * g * c - 10.0f * c * c;
        #pragma unroll
        for (int o = 16; o; o >>= 1) p += __shfl_xor_sync(0xffffffffu, p, o);
        if ((tid & 31) == 0) red[tid >> 5] = p;
    }
    __syncthreads();

    // alignment split
    uintptr_t a = (uintptr_t)lrow;
    const int lead = (int)(((16u - (unsigned)(a & 15u)) & 15u) >> 2);   // 0..3
    const int nv4  = (VV - lead) >> 2;
    const int tail0 = lead + nv4 * 4;
    const float4* __restrict__ l4 = reinterpret_cast<const float4*>(lrow + lead);

    // ------------- single-pass collect @ static threshold -------------
    float T = T0;
    for (int i = tid; i < lead; i += NT) {
        float x = lrow[i];
        if (x >= T) {
            int p = atomicAdd(&scnt, 1);
            if (p < BUFCAP) buf[p] = make_comp(x, (unsigned)i);
        }
    }
    #pragma unroll 8
    for (int i = tid; i < nv4; i += NT) {
        float4 x = l4[i];
        unsigned pr = (x.x >= T ? 1u : 0u) | (x.y >= T ? 2u : 0u)
                    | (x.z >= T ? 4u : 0u) | (x.w >= T ? 8u : 0u);
        if (pr) {
            int base = atomicAdd(&scnt, __popc(pr));
            float vals[4] = { x.x, x.y, x.z, x.w };
            unsigned g0 = (unsigned)(lead + 4 * i);
            #pragma unroll
            for (int c = 0; c < 4; ++c) {
                if (pr & (1u << c)) {
                    if (base < BUFCAP) buf[base] = make_comp(vals[c], g0 + c);
                    ++base;
                }
            }
        }
    }
    for (int i = tail0 + tid; i < VV; i += NT) {
        float x = lrow[i];
        if (x >= T) {
            int p = atomicAdd(&scnt, 1);
            if (p < BUFCAP) buf[p] = make_comp(x, (unsigned)i);
        }
    }
    __syncthreads();
    if (tid == 0) fctl[3] = red[0] + red[1];   // c0
    int C = scnt;

    // ------------- rare fallback: exact adaptive threshold (gmem/L2) -------------
    if (C < KSEL || C > BUFCAP) {
        __syncthreads();
        float mx = -FLT_MAX, mn = FLT_MAX;
        for (int i = tid; i < VV; i += NT) {
            float x = lrow[i];
            mx = fmaxf(mx, x); mn = fminf(mn, x);
        }
        #pragma unroll
        for (int o = 16; o; o >>= 1) {
            mx = fmaxf(mx, __shfl_xor_sync(0xffffffffu, mx, o));
            mn = fminf(mn, __shfl_xor_sync(0xffffffffu, mn, o));
        }
        if ((tid & 31) == 0) { red[tid >> 5] = mx; red[8 + (tid >> 5)] = mn; }
        __syncthreads();
        if (tid == 0) {
            float M = -FLT_MAX, m = FLT_MAX;
            for (int w = 0; w < 8; ++w) {
                M = fmaxf(M, red[w]); m = fminf(m, red[8 + w]);
            }
            if (C > BUFCAP) { fctl[0] = T0; fctl[1] = M;  ictl[1] = C;  }
            else            { fctl[0] = m;  fctl[1] = T0; ictl[1] = VV; }
            ictl[0] = 0;
            icnt[0] = icnt[1] = icnt[2] = icnt[3] = 0;
        }
        __syncthreads();
        for (int it = 0; it < 30; ++it) {
            if (ictl[0]) break;
            float lo = fctl[0], hi = fctl[1];
            float step = (hi - lo) * 0.2f;
            float t0 = lo + step, t1 = lo + 2.f*step, t2 = lo + 3.f*step, t3 = lo + 4.f*step;
            int c0 = 0, c1 = 0, c2 = 0, c3 = 0;
            for (int i = tid; i < VV; i += NT) {
                float x = lrow[i];
                c0 += (x >= t0); c1 += (x >= t1); c2 += (x >= t2); c3 += (x >= t3);
            }
            #pragma unroll
            for (int o = 16; o; o >>= 1) {
                c0 += __shfl_xor_sync(0xffffffffu, c0, o);
                c1 += __shfl_xor_sync(0xffffffffu, c1, o);
                c2 += __shfl_xor_sync(0xffffffffu, c2, o);
                c3 += __shfl_xor_sync(0xffffffffu, c3, o);
            }
            if ((tid & 31) == 0) {
                atomicAdd(&icnt[0], c0); atomicAdd(&icnt[1], c1);
                atomicAdd(&icnt[2], c2); atomicAdd(&icnt[3], c3);
            }
            __syncthreads();
            if (tid == 0) {
                int   n[5]  = { ictl[1], icnt[0], icnt[1], icnt[2], icnt[3] };
                float tt[5] = { lo, t0, t1, t2, t3 };
                int j = 0;
                for (int q = 1; q < 5; ++q) if (n[q] >= KSEL) j = q;
                bool degen = !(t0 > lo && t3 < hi);
                if (n[j] <= BUFCAP || degen || it == 29) {
                    fctl[2] = tt[j]; ictl[0] = 1;
                } else {
                    fctl[0] = tt[j]; ictl[1] = n[j];
                    fctl[1] = (j < 4) ? tt[j + 1] : hi;
                }
                icnt[0] = icnt[1] = icnt[2] = icnt[3] = 0;
            }
            __syncthreads();
        }
        T = fctl[2];
        if (tid == 0) scnt = 0;
        __syncthreads();
        // recollect at final T
        for (int i = tid; i < lead; i += NT) {
            float x = lrow[i];
            if (x >= T) {
                int p = atomicAdd(&scnt, 1);
                if (p < BUFCAP) buf[p] = make_comp(x, (unsigned)i);
            }
        }
        for (int i = tid; i < nv4; i += NT) {
            float4 x = l4[i];
            unsigned pr = (x.x >= T ? 1u : 0u) | (x.y >= T ? 2u : 0u)
                        | (x.z >= T ? 4u : 0u) | (x.w >= T ? 8u : 0u);
            if (pr) {
                int base = atomicAdd(&scnt, __popc(pr));
                float vals[4] = { x.x, x.y, x.z, x.w };
                unsigned g0 = (unsigned)(lead + 4 * i);
                #pragma unroll
                for (int c = 0; c < 4; ++c) {
                    if (pr & (1u << c)) {
                        if (base < BUFCAP) buf[base] = make_comp(vals[c], g0 + c);
                        ++base;
                    }
                }
            }
        }
        for (int i = tail0 + tid; i < VV; i += NT) {
            float x = lrow[i];
            if (x >= T) {
                int p = atomicAdd(&scnt, 1);
                if (p < BUFCAP) buf[p] = make_comp(x, (unsigned)i);
            }
        }
        __syncthreads();
        C = scnt;
    }

    const int n = min(C, BUFCAP);
    for (int i = n + tid; i < BUFCAP; i += NT) buf[i] = 0ull;

    // ------------- bitonic sort 512 composites, descending -------------
    // 256 threads -> exactly one compare-exchange per thread per stage
    for (unsigned k = 2; k <= BUFCAP; k <<= 1) {
        for (unsigned j = k >> 1; j > 0; j >>= 1) {
            __syncthreads();
            unsigned i = ((unsigned)tid << 1) - ((unsigned)tid & (j - 1));
            unsigned p = i | j;
            unsigned long long x = buf[i], y = buf[p];
            bool desc = ((i & k) == 0);
            if (desc ? (x < y) : (x > y)) { buf[i] = y; buf[p] = x; }
        }
    }
    __syncthreads();

    // ------------- gather: 250 dots against W (two items per thread) -------------
    #pragma unroll
    for (int s = 0; s < 2; ++s) {
        int t = tid + s * NT;
        if (t < KSEL) {
            unsigned idx = ~((unsigned)(buf[t] & 0xffffffffull));
            const float4* wr = reinterpret_cast<const float4*>(W + (size_t)idx * EE);
            const float4* u4 = reinterpret_cast<const float4*>(su);
            float acc = 0.f, wsq = 0.f;
            #pragma unroll
            for (int q = 0; q < EE / 4; ++q) {
                float4 w = wr[q], u = u4[q];
                acc += w.x * u.x + w.y * u.y + w.z * u.z + w.w * u.w;
                wsq += w.x * w.x + w.y * w.y + w.z * w.z + w.w * w.w;
            }
            size_t o = (size_t)row * KSEL + (size_t)t;
            out[o] = acc - 10.0f * wsq + fctl[3];
            out[(size_t)NROWS * KSEL + o] = (float)idx;
        }
    }
}

extern "C" void kernel_launch(void* const* d_in, const int* in_sizes, int n_in,
                              void* d_out, int out_size)
{
    (void)in_sizes; (void)n_in; (void)out_size;
    lang_topk_kernel<<<NROWS, NT>>>(
        (const float*)d_in[0], (const float*)d_in[1],
        (const float*)d_in[2], (const float*)d_in[3], (float*)d_out);
}

// round 5
// speedup vs baseline: 3.0386x; 1.1771x over previous
#include <cuda_runtime.h>
#include <cstdint>
#include <float.h>

#define NROWS  2048
#define VV     50257
#define EE     64
#define KSEL   250
#define NT     256
#define BUFCAP 512
#define CH     4
#define SLOT   512
#define T0     2.45f

__device__ unsigned long long g_cand[(size_t)NROWS * CH * SLOT];  // 33.5 MB scratch
__device__ int                g_cnt[NROWS * CH];

__device__ __forceinline__ unsigned long long make_comp(float x, unsigned gidx) {
    unsigned ub  = __float_as_uint(x);
    unsigned key = (ub & 0x80000000u) ? ~ub : (ub | 0x80000000u);
    return ((unsigned long long)key << 32) | (unsigned)(~gidx);
}

// ---------------------------------------------------------------------------
// Kernel 1: pure streaming collect. One CTA per quarter-row.
// ---------------------------------------------------------------------------
__global__ void __launch_bounds__(NT, 8) collect_kernel(const float* __restrict__ logits)
{
    __shared__ int scnt;
    const int tid = threadIdx.x;
    const int chunk = blockIdx.x;
    const int row = blockIdx.y;
    const float* __restrict__ lrow = logits + (size_t)row * VV;
    if (tid == 0) scnt = 0;
    __syncthreads();

    uintptr_t a = (uintptr_t)lrow;
    const int lead  = (int)(((16u - (unsigned)(a & 15u)) & 15u) >> 2);
    const int nv4   = (VV - lead) >> 2;
    const int tail0 = lead + nv4 * 4;
    const float4* __restrict__ l4 = reinterpret_cast<const float4*>(lrow + lead);
    unsigned long long* __restrict__ slot = g_cand + ((size_t)(row * CH + chunk)) * SLOT;

    const int c4 = (nv4 + CH - 1) / CH;
    const int b4 = chunk * c4;
    const int e4 = min(b4 + c4, nv4);

    if (chunk == 0) {
        for (int i = tid; i < lead; i += NT) {
            float x = lrow[i];
            if (x >= T0) {
                int p = atomicAdd(&scnt, 1);
                if (p < SLOT) slot[p] = make_comp(x, (unsigned)i);
            }
        }
    }
    if (chunk == CH - 1) {
        for (int i = tail0 + tid; i < VV; i += NT) {
            float x = lrow[i];
            if (x >= T0) {
                int p = atomicAdd(&scnt, 1);
                if (p < SLOT) slot[p] = make_comp(x, (unsigned)i);
            }
        }
    }
    #pragma unroll 4
    for (int i = b4 + tid; i < e4; i += NT) {
        float4 x = __ldcs(&l4[i]);
        unsigned pr = (x.x >= T0 ? 1u : 0u) | (x.y >= T0 ? 2u : 0u)
                    | (x.z >= T0 ? 4u : 0u) | (x.w >= T0 ? 8u : 0u);
        if (pr) {
            int base = atomicAdd(&scnt, __popc(pr));
            float vals[4] = { x.x, x.y, x.z, x.w };
            unsigned g0 = (unsigned)(lead + 4 * i);
            #pragma unroll
            for (int c = 0; c < 4; ++c) {
                if (pr & (1u << c)) {
                    if (base < SLOT) slot[base] = make_comp(vals[c], g0 + c);
                    ++base;
                }
            }
        }
    }
    __syncthreads();
    if (tid == 0) g_cnt[row * CH + chunk] = scnt;
}

// ---------------------------------------------------------------------------
// Kernel 2: per-row sort + gather (+ exact fallback for non-Gaussian inputs)
// ---------------------------------------------------------------------------
__global__ void __launch_bounds__(NT, 6) select_kernel(
    const float* __restrict__ gx, const float* __restrict__ cb,
    const float* __restrict__ W,  const float* __restrict__ logits,
    float* __restrict__ out)
{
    __shared__ unsigned long long buf[BUFCAP];
    __shared__ float su[EE];
    __shared__ float red[16];
    __shared__ int   scnt;
    __shared__ int   icnt[4];
    __shared__ float fctl[4];   // [0]=lo [1]=hi [2]=Tsel [3]=c0
    __shared__ int   ictl[2];
    __shared__ int   soff[CH + 1];
    __shared__ int   sbad;

    const int tid = threadIdx.x;
    const int row = blockIdx.x;
    const float* __restrict__ lrow = logits + (size_t)row * VV;

    // u vector + c0 partials
    if (tid < EE) {
        float g = gx[row * EE + tid], c = cb[row * EE + tid];
        su[tid] = -0.5f * g + 20.0f * c;
        float p = 0.5f * g * c - 10.0f * c * c;
        #pragma unroll
        for (int o = 16; o; o >>= 1) p += __shfl_xor_sync(0xffffffffu, p, o);
        if ((tid & 31) == 0) red[tid >> 5] = p;
    }
    if (tid == 0) {
        int off = 0;
        bool bad = false;
        #pragma unroll
        for (int j = 0; j < CH; ++j) {
            soff[j] = off;
            int c = g_cnt[row * CH + j];
            if (c > SLOT) bad = true;
            off += c;
        }
        soff[CH] = off;
        sbad = (bad || off < KSEL || off > BUFCAP) ? 1 : 0;
    }
    __syncthreads();
    if (tid == 0) fctl[3] = red[0] + red[1];   // c0
    int C;

    if (!sbad) {
        C = soff[CH];
        #pragma unroll
        for (int j = 0; j < CH; ++j) {
            const unsigned long long* __restrict__ slot =
                g_cand + ((size_t)(row * CH + j)) * SLOT;
            int n = soff[j + 1] - soff[j];
            for (int i = tid; i < n; i += NT) buf[soff[j] + i] = slot[i];
        }
        __syncthreads();
    } else {
        // ---------- exact adaptive fallback (rare) ----------
        float mx = -FLT_MAX, mn = FLT_MAX;
        for (int i = tid; i < VV; i += NT) {
            float x = lrow[i];
            mx = fmaxf(mx, x); mn = fminf(mn, x);
        }
        #pragma unroll
        for (int o = 16; o; o >>= 1) {
            mx = fmaxf(mx, __shfl_xor_sync(0xffffffffu, mx, o));
            mn = fminf(mn, __shfl_xor_sync(0xffffffffu, mn, o));
        }
        if ((tid & 31) == 0) { red[tid >> 5] = mx; red[8 + (tid >> 5)] = mn; }
        __syncthreads();
        if (tid == 0) {
            float M = -FLT_MAX, m = FLT_MAX;
            for (int w = 0; w < 8; ++w) {
                M = fmaxf(M, red[w]); m = fminf(m, red[8 + w]);
            }
            fctl[0] = m; fctl[1] = M; ictl[1] = VV;
            ictl[0] = 0;
            icnt[0] = icnt[1] = icnt[2] = icnt[3] = 0;
        }
        __syncthreads();
        for (int it = 0; it < 30; ++it) {
            if (ictl[0]) break;
            float lo = fctl[0], hi = fctl[1];
            float step = (hi - lo) * 0.2f;
            float t0 = lo + step, t1 = lo + 2.f*step, t2 = lo + 3.f*step, t3 = lo + 4.f*step;
            int c0 = 0, c1 = 0, c2 = 0, c3 = 0;
            for (int i = tid; i < VV; i += NT) {
                float x = lrow[i];
                c0 += (x >= t0); c1 += (x >= t1); c2 += (x >= t2); c3 += (x >= t3);
            }
            #pragma unroll
            for (int o = 16; o; o >>= 1) {
                c0 += __shfl_xor_sync(0xffffffffu, c0, o);
                c1 += __shfl_xor_sync(0xffffffffu, c1, o);
                c2 += __shfl_xor_sync(0xffffffffu, c2, o);
                c3 += __shfl_xor_sync(0xffffffffu, c3, o);
            }
            if ((tid & 31) == 0) {
                atomicAdd(&icnt[0], c0); atomicAdd(&icnt[1], c1);
                atomicAdd(&icnt[2], c2); atomicAdd(&icnt[3], c3);
            }
            __syncthreads();
            if (tid == 0) {
                int   n[5]  = { ictl[1], icnt[0], icnt[1], icnt[2], icnt[3] };
                float tt[5] = { lo, t0, t1, t2, t3 };
                int j = 0;
                for (int q = 1; q < 5; ++q) if (n[q] >= KSEL) j = q;
                bool degen = !(t0 > lo && t3 < hi);
                if (n[j] <= BUFCAP || degen || it == 29) {
                    fctl[2] = tt[j]; ictl[0] = 1;
                } else {
                    fctl[0] = tt[j]; ictl[1] = n[j];
                    fctl[1] = (j < 4) ? tt[j + 1] : hi;
                }
                icnt[0] = icnt[1] = icnt[2] = icnt[3] = 0;
            }
            __syncthreads();
        }
        float T = fctl[2];
        if (tid == 0) scnt = 0;
        __syncthreads();
        for (int i = tid; i < VV; i += NT) {
            float x = lrow[i];
            if (x >= T) {
                int p = atomicAdd(&scnt, 1);
                if (p < BUFCAP) buf[p] = make_comp(x, (unsigned)i);
            }
        }
        __syncthreads();
        C = scnt;
    }

    const int n = min(C, BUFCAP);
    for (int i = n + tid; i < BUFCAP; i += NT) buf[i] = 0ull;

    // bitonic sort 512 composites, descending (one CAS per thread per stage)
    for (unsigned k = 2; k <= BUFCAP; k <<= 1) {
        for (unsigned j = k >> 1; j > 0; j >>= 1) {
            __syncthreads();
            unsigned i = ((unsigned)tid << 1) - ((unsigned)tid & (j - 1));
            unsigned p = i | j;
            unsigned long long x = buf[i], y = buf[p];
            bool desc = ((i & k) == 0);
            if (desc ? (x < y) : (x > y)) { buf[i] = y; buf[p] = x; }
        }
    }
    __syncthreads();

    // gather: 250 dots against W
    #pragma unroll
    for (int s = 0; s < 2; ++s) {
        int t = tid + s * NT;
        if (t < KSEL) {
            unsigned idx = ~((unsigned)(buf[t] & 0xffffffffull));
            const float4* wr = reinterpret_cast<const float4*>(W + (size_t)idx * EE);
            const float4* u4 = reinterpret_cast<const float4*>(su);
            float acc = 0.f, wsq = 0.f;
            #pragma unroll
            for (int q = 0; q < EE / 4; ++q) {
                float4 w = wr[q], u = u4[q];
                acc += w.x * u.x + w.y * u.y + w.z * u.z + w.w * u.w;
                wsq += w.x * w.x + w.y * w.y + w.z * w.z + w.w * w.w;
            }
            size_t o = (size_t)row * KSEL + (size_t)t;
            out[o] = acc - 10.0f * wsq + fctl[3];
            out[(size_t)NROWS * KSEL + o] = (float)idx;
        }
    }
}

extern "C" void kernel_launch(void* const* d_in, const int* in_sizes, int n_in,
                              void* d_out, int out_size)
{
    (void)in_sizes; (void)n_in; (void)out_size;
    const float* gx = (const float*)d_in[0];
    const float* cb = (const float*)d_in[1];
    const float* W  = (const float*)d_in[2];
    const float* lg = (const float*)d_in[3];
    collect_kernel<<<dim3(CH, NROWS), NT>>>(lg);
    select_kernel<<<NROWS, NT>>>(gx, cb, W, lg, (float*)d_out);
}